// round 17
// baseline (speedup 1.0000x reference)
#include <cuda_runtime.h>
#include <cuda_fp16.h>
#include <cstdint>

#define B_  8
#define S1_ 2048
#define S2_ 2048
#define D_  512
#define F_  256
#define NQKV (B_ * S1_ * F_)
#define NFEAT (B_ * S1_ * D_)
#define NP   (B_ * S1_ * S2_)

__device__ __align__(16) __half g_f1 [NFEAT];
__device__ __align__(16) __half g_f2 [NFEAT];
__device__ __align__(16) __half g_wq[D_ * F_];      // transposed
__device__ __align__(16) __half g_wk[D_ * F_];
__device__ __align__(16) __half g_w2[D_ * F_];      // (Wv@Wfc)^T
__device__ __align__(16) float  g_c2[F_];
__device__ __align__(16) float  g_zero[F_];
__device__ __align__(16) __half g_Q  [NQKV];
__device__ __align__(16) __half g_K  [NQKV];
__device__ __align__(16) __half g_VT [NQKV];        // [b, f, t]
__device__ __align__(16) __half g_P  [NP];
__device__ __align__(16) float  g_lp [B_ * S1_ * 16];
__device__ __align__(16) float  g_l  [B_ * S1_];

__device__ __forceinline__ uint32_t smem_to_u32(const void* p) {
    uint32_t a;
    asm("{ .reg .u64 t; cvta.to.shared.u64 t, %1; cvt.u32.u64 %0, t; }" : "=r"(a) : "l"(p));
    return a;
}
__device__ __forceinline__ void ldsm4(uint32_t* r, uint32_t a) {
    asm volatile("ldmatrix.sync.aligned.m8n8.x4.shared.b16 {%0,%1,%2,%3}, [%4];"
        : "=r"(r[0]), "=r"(r[1]), "=r"(r[2]), "=r"(r[3]) : "r"(a));
}
__device__ __forceinline__ void mma_f16(float (&d)[4], const uint32_t* a, uint32_t b0, uint32_t b1) {
    asm volatile("mma.sync.aligned.m16n8k16.row.col.f32.f16.f16.f32 "
        "{%0,%1,%2,%3}, {%4,%5,%6,%7}, {%8,%9}, {%0,%1,%2,%3};"
        : "+f"(d[0]), "+f"(d[1]), "+f"(d[2]), "+f"(d[3])
        : "r"(a[0]), "r"(a[1]), "r"(a[2]), "r"(a[3]), "r"(b0), "r"(b1));
}
__device__ __forceinline__ uint32_t pack2(__half a, __half b) {
    return (uint32_t)__half_as_ushort(a) | ((uint32_t)__half_as_ushort(b) << 16);
}
#define CP_ASYNC16(dst, src) asm volatile("cp.async.cg.shared.global [%0], [%1], 16;" :: "r"(dst), "l"(src))
#define CP_COMMIT() asm volatile("cp.async.commit_group;" ::: "memory")
#define CP_WAIT0()  asm volatile("cp.async.wait_group 0;" ::: "memory")
#define CP_WAIT1()  asm volatile("cp.async.wait_group 1;" ::: "memory")

// ---------------------------------------------------------------------------
// Fused prologue: one launch does everything before the GEMMs.
//  blocks [0, 8192)        : feat1 -> fp16
//  blocks [8192, 16384)    : feat2 -> fp16
//  blocks [16384, 17408)   : Wq/Wk -> fp16 transposed
//  blocks [17408, 17440)   : W2 = Wv@Wfc -> fp16 transposed (16 rows/block)
//  block  17440            : c2 = bv@Wfc + bfc
// ---------------------------------------------------------------------------
#define NCONV (NFEAT / 4 / 256)          // 8192
#define PRO_BLOCKS (2 * NCONV + 1024 + 32 + 1)

__global__ void __launch_bounds__(256) prologue_kernel(
    const float* __restrict__ feat1, const float* __restrict__ feat2,
    const float* __restrict__ Wq, const float* __restrict__ Wk,
    const float* __restrict__ Wv, const float* __restrict__ Wfc,
    const float* __restrict__ bv, const float* __restrict__ bfc,
    __half* __restrict__ f1, __half* __restrict__ f2,
    __half* __restrict__ wq, __half* __restrict__ wk,
    __half* __restrict__ w2, float* __restrict__ c2)
{
    const int bid = blockIdx.x;
    const int tid = threadIdx.x;

    if (bid < 2 * NCONV) {                       // feature converts
        const float* in = bid < NCONV ? feat1 : feat2;
        __half* o       = bid < NCONV ? f1 : f2;
        int i = (bid < NCONV ? bid : bid - NCONV) * 256 + tid;
        float4 v = ((const float4*)in)[i];
        ((uint2*)o)[i] = make_uint2(
            pack2(__float2half_rn(v.x), __float2half_rn(v.y)),
            pack2(__float2half_rn(v.z), __float2half_rn(v.w)));
        return;
    }
    if (bid < 2 * NCONV + 1024) {                // Wq/Wk transpose converts
        int i = (bid - 2 * NCONV) * 256 + tid;
        const int NW = D_ * F_;
        int which = i / NW, j = i - which * NW;
        int n = j / D_, k = j - n * D_;
        (which == 0 ? wq : wk)[j] =
            __float2half_rn((which == 0 ? Wq : Wk)[(size_t)k * F_ + n]);
        return;
    }
    if (bid == 2 * NCONV + 1024 + 32) {          // c2
        const int n = tid;
        float part[4] = {0, 0, 0, 0};
        for (int jb = 0; jb < F_; jb += 4)
            #pragma unroll
            for (int u = 0; u < 4; u++)
                part[u] += bv[jb + u] * Wfc[(size_t)(jb + u) * F_ + n];
        c2[n] = bfc[n] + (part[0] + part[1]) + (part[2] + part[3]);
        return;
    }
    // W2: 16 Wv-rows per block, Wv tile in smem -> 16 FMA per Wfc load
    {
        const int kb = bid - (2 * NCONV + 1024); // 0..31
        const int n = tid;
        __shared__ float wv[16][F_];
        #pragma unroll
        for (int r = 0; r < 16; r++)
            wv[r][n] = Wv[(size_t)(kb * 16 + r) * F_ + n];
        __syncthreads();
        float acc[16];
        #pragma unroll
        for (int r = 0; r < 16; r++) acc[r] = 0.f;
        #pragma unroll 2
        for (int j = 0; j < F_; j++) {
            float wf = Wfc[(size_t)j * F_ + n];
            #pragma unroll
            for (int r = 0; r < 16; r++) acc[r] += wv[r][j] * wf;
        }
        size_t i0 = (size_t)n * D_ + kb * 16;
        #pragma unroll
        for (int r = 0; r < 16; r++) w2[i0 + r] = __float2half_rn(acc[r]);
    }
}

// ---------------------------------------------------------------------------
// Shared HMMA GEMM body: CTA 128x128, 8 warps (2m x 4n), warp 64x32,
// k-block 32, 3-stage cp.async (96KB), single-chain pure fp16.
// ---------------------------------------------------------------------------
#define GEMM_SMEM 98304

#define GEMM_PROLOG \
    extern __shared__ char sm[]; \
    const uint32_t smb = smem_to_u32(sm); \
    const int tid = threadIdx.x, lane = tid & 31, wid = tid >> 5; \
    const int wm = wid & 1, wn = wid >> 1; \
    const int arow = wm * 64 + (lane & 15); \
    const int as = arow & 7, ah = lane >> 4; \
    const int brow = wn * 32 + ((lane >> 4) << 3) + (lane & 7); \
    const int bs = lane & 7, bh2 = (lane >> 3) & 1; \
    const int lq = lane & 3;

#define GISSUE(buf, k0, KDV) do { \
    uint32_t gb = smb + (buf) * 32768; \
    _Pragma("unroll") \
    for (int p = 0; p < 4; p++) { \
        int id = p * 256 + tid; int r = id >> 3, c = id & 7; \
        if (c < 4) { \
            uint32_t d = r * 128 + (((uint32_t)(c ^ (r & 7))) << 4); \
            CP_ASYNC16(gb + d,         Ag + (size_t)(ma + r) * (KDV) + (k0) + c * 8); \
            CP_ASYNC16(gb + 16384 + d, Bg + (size_t)(nb + r) * (KDV) + (k0) + c * 8); \
        } \
    } } while (0)

#define GEMM_MAIN(KDV) \
    float acc[4][4][4]; \
    _Pragma("unroll") \
    for (int i = 0; i < 4; i++) \
        _Pragma("unroll") \
        for (int j = 0; j < 4; j++) \
            _Pragma("unroll") \
            for (int k = 0; k < 4; k++) acc[i][j][k] = 0.f; \
    { \
        const int T = (KDV) / 32; \
        GISSUE(0, 0, KDV); CP_COMMIT(); \
        if (T > 1) { GISSUE(1, 32, KDV); CP_COMMIT(); } \
        for (int t = 0; t < T; t++) { \
            if (t + 1 < T) { CP_WAIT1(); } else { CP_WAIT0(); } \
            __syncthreads(); \
            if (t + 2 < T) { GISSUE((t + 2) % 3, (t + 2) * 32, KDV); CP_COMMIT(); } \
            const int cur = t % 3; \
            uint32_t aP = smb + cur * 32768 + arow * 128; \
            uint32_t bP = smb + cur * 32768 + 16384 + brow * 128; \
            _Pragma("unroll") \
            for (int ks = 0; ks < 2; ks++) { \
                uint32_t hcA = (uint32_t)(2 * ks + ah); \
                uint32_t aq[4][4]; \
                _Pragma("unroll") \
                for (int mi = 0; mi < 4; mi++) \
                    ldsm4(aq[mi], aP + mi * 2048 + ((hcA ^ (uint32_t)as) << 4)); \
                uint32_t hcB = (uint32_t)(2 * ks + bh2); \
                _Pragma("unroll") \
                for (int ni = 0; ni < 2; ni++) { \
                    uint32_t bhh[4]; \
                    ldsm4(bhh, bP + ni * 2048 + ((hcB ^ (uint32_t)bs) << 4)); \
                    _Pragma("unroll") \
                    for (int mi = 0; mi < 4; mi++) { \
                        mma_f16(acc[mi][2*ni],   aq[mi], bhh[0], bhh[1]); \
                        mma_f16(acc[mi][2*ni+1], aq[mi], bhh[2], bhh[3]); \
                    } \
                } \
            } \
        } \
        __syncthreads(); \
    }

// ---------------------------------------------------------------------------
// Fused Q/K/V' projections: single chain, plain fp16.
// z=0 Q, z=1 K (row-major), z=2 V'T (transposed [b,f,t]).
// ---------------------------------------------------------------------------
__global__ void __launch_bounds__(256, 2) gemm_qkv(
    const __half* __restrict__ f1, const __half* __restrict__ f2,
    const __half* __restrict__ wq, const __half* __restrict__ wk,
    const __half* __restrict__ w2,
    const float* __restrict__ bq, const float* __restrict__ bk, const float* __restrict__ bz,
    __half* __restrict__ Q, __half* __restrict__ K, __half* __restrict__ VT)
{
    GEMM_PROLOG
    const int n0 = blockIdx.x * 128, m0 = blockIdx.y * 128;
    const int z = blockIdx.z;
    const int ma = m0, nb = n0;
    const __half* Ag = z == 0 ? f1 : f2;
    const __half* Bg = z == 0 ? wq : (z == 1 ? wk : w2);
    const float* bias = z == 0 ? bq : (z == 1 ? bk : bz);
    __half* O = z == 0 ? Q : (z == 1 ? K : VT);

    GEMM_MAIN(D_)

    #pragma unroll
    for (int mi = 0; mi < 4; mi++) {
        int r0 = m0 + wm * 64 + mi * 16 + (lane >> 2);
        int r1 = r0 + 8;
        #pragma unroll
        for (int nt = 0; nt < 4; nt++) {
            int col = n0 + wn * 32 + nt * 8 + 2 * lq;
            float b0 = bias[col], b1 = bias[col + 1];
            __half h0 = __float2half_rn(acc[mi][nt][0] + b0);
            __half h1 = __float2half_rn(acc[mi][nt][1] + b1);
            __half h2 = __float2half_rn(acc[mi][nt][2] + b0);
            __half h3 = __float2half_rn(acc[mi][nt][3] + b1);
            if (z < 2) {
                *(uint32_t*)(O + (size_t)r0 * 256 + col) = pack2(h0, h1);
                *(uint32_t*)(O + (size_t)r1 * 256 + col) = pack2(h2, h3);
            } else {
                size_t o0 = (size_t)(r0 >> 11) * (F_ * S2_) + (size_t)col * S2_ + (r0 & 2047);
                size_t o1 = (size_t)(r1 >> 11) * (F_ * S2_) + (size_t)col * S2_ + (r1 & 2047);
                O[o0] = h0; O[o0 + S2_] = h1;
                O[o1] = h2; O[o1 + S2_] = h3;
            }
        }
    }
}

// ---------------------------------------------------------------------------
// S-kernel: P = exp(scale * Q@K^T) fp16 + per-128-block row sums.
// ---------------------------------------------------------------------------
__global__ void __launch_bounds__(256, 2) gemm_S(
    const __half* __restrict__ Q, const __half* __restrict__ K,
    __half* __restrict__ P, float* __restrict__ lp)
{
    GEMM_PROLOG
    const int kblk = blockIdx.x, qblk = blockIdx.y, b = blockIdx.z;
    const int ma = qblk * 128, nb = kblk * 128;
    const __half* Ag = Q + (size_t)b * S1_ * F_;
    const __half* Bg = K + (size_t)b * S2_ * F_;

    GEMM_MAIN(F_)

    const float scale = 0.0625f;
    const int bq0 = b * S1_ + qblk * 128;
    const int kb0 = kblk * 128;
    float rsum[4][2];
    #pragma unroll
    for (int mi = 0; mi < 4; mi++) { rsum[mi][0] = 0.f; rsum[mi][1] = 0.f; }

    #pragma unroll
    for (int mi = 0; mi < 4; mi++) {
        int rl0 = wm * 64 + mi * 16 + (lane >> 2);
        size_t pb0 = (size_t)(bq0 + rl0) * S2_ + kb0;
        size_t pb1 = (size_t)(bq0 + rl0 + 8) * S2_ + kb0;
        #pragma unroll
        for (int nt = 0; nt < 4; nt++) {
            int col = wn * 32 + nt * 8 + 2 * lq;
            float p0 = __expf(acc[mi][nt][0] * scale);
            float p1 = __expf(acc[mi][nt][1] * scale);
            float p2 = __expf(acc[mi][nt][2] * scale);
            float p3 = __expf(acc[mi][nt][3] * scale);
            rsum[mi][0] += p0 + p1;
            rsum[mi][1] += p2 + p3;
            *(uint32_t*)(P + pb0 + col) = pack2(__float2half_rn(p0), __float2half_rn(p1));
            *(uint32_t*)(P + pb1 + col) = pack2(__float2half_rn(p2), __float2half_rn(p3));
        }
    }
    #pragma unroll
    for (int mi = 0; mi < 4; mi++) {
        #pragma unroll
        for (int u = 0; u < 2; u++) {
            rsum[mi][u] += __shfl_xor_sync(0xffffffffu, rsum[mi][u], 1);
            rsum[mi][u] += __shfl_xor_sync(0xffffffffu, rsum[mi][u], 2);
        }
    }
    float* red = (float*)sm;
    __syncthreads();
    if (lq == 0) {
        #pragma unroll
        for (int mi = 0; mi < 4; mi++) {
            int rl = wm * 64 + mi * 16 + (lane >> 2);
            red[wn * 128 + rl]     = rsum[mi][0];
            red[wn * 128 + rl + 8] = rsum[mi][1];
        }
    }
    __syncthreads();
    if (tid < 128)
        lp[(size_t)(bq0 + tid) * 16 + kblk] =
            (red[tid] + red[128 + tid]) + (red[256 + tid] + red[384 + tid]);
}

__global__ void __launch_bounds__(256) lreduce_kernel(const float* __restrict__ lp,
                                                      float* __restrict__ l)
{
    int i = blockIdx.x * 256 + threadIdx.x;
    if (i >= B_ * S1_) return;
    float s = 0.f;
    #pragma unroll
    for (int j = 0; j < 16; j++) s += lp[(size_t)i * 16 + j];
    l[i] = s;
}

// ---------------------------------------------------------------------------
// PV-kernel: out = (P@VT^T)/l + c2 (final fp32 output).
// ---------------------------------------------------------------------------
__global__ void __launch_bounds__(256, 2) gemm_pv(
    const __half* __restrict__ P, const __half* __restrict__ VT,
    const float* __restrict__ l, const float* __restrict__ c2,
    float* __restrict__ out)
{
    GEMM_PROLOG
    const int fblk = blockIdx.x, qblk = blockIdx.y, b = blockIdx.z;
    const int ma = qblk * 128, nb = fblk * 128;
    const __half* Ag = P + (size_t)b * S1_ * S2_;
    const __half* Bg = VT + (size_t)b * F_ * S2_;

    GEMM_MAIN(S2_)

    const int bq0 = b * S1_ + qblk * 128;
    #pragma unroll
    for (int mi = 0; mi < 4; mi++) {
        int rl0 = wm * 64 + mi * 16 + (lane >> 2);
        float inv0 = 1.f / l[bq0 + rl0];
        float inv1 = 1.f / l[bq0 + rl0 + 8];
        size_t o0 = (size_t)(bq0 + rl0) * 256;
        size_t o1 = (size_t)(bq0 + rl0 + 8) * 256;
        #pragma unroll
        for (int nt = 0; nt < 4; nt++) {
            int col = fblk * 128 + wn * 32 + nt * 8 + 2 * lq;
            float c0 = c2[col], c1 = c2[col + 1];
            *(float2*)(out + o0 + col) =
                make_float2(acc[mi][nt][0] * inv0 + c0, acc[mi][nt][1] * inv0 + c1);
            *(float2*)(out + o1 + col) =
                make_float2(acc[mi][nt][2] * inv1 + c0, acc[mi][nt][3] * inv1 + c1);
        }
    }
}

// ---------------------------------------------------------------------------
extern "C" void kernel_launch(void* const* d_in, const int* in_sizes, int n_in,
                              void* d_out, int out_size)
{
    const float* feat1 = (const float*)d_in[0];
    const float* feat2 = (const float*)d_in[1];
    const float* Wq    = (const float*)d_in[2];
    const float* bq    = (const float*)d_in[3];
    const float* Wk    = (const float*)d_in[4];
    const float* bk    = (const float*)d_in[5];
    const float* Wv    = (const float*)d_in[6];
    const float* bv    = (const float*)d_in[7];
    const float* Wfc   = (const float*)d_in[8];
    const float* bfc   = (const float*)d_in[9];
    float* out = (float*)d_out;

    __half *f1, *f2, *Q, *K, *VT, *P, *wq, *wk, *w2;
    float *lp, *lv, *c2, *zv;
    cudaGetSymbolAddress((void**)&f1,  g_f1);
    cudaGetSymbolAddress((void**)&f2,  g_f2);
    cudaGetSymbolAddress((void**)&wq,  g_wq);
    cudaGetSymbolAddress((void**)&wk,  g_wk);
    cudaGetSymbolAddress((void**)&w2,  g_w2);
    cudaGetSymbolAddress((void**)&c2,  g_c2);
    cudaGetSymbolAddress((void**)&zv,  g_zero);
    cudaGetSymbolAddress((void**)&Q,   g_Q);
    cudaGetSymbolAddress((void**)&K,   g_K);
    cudaGetSymbolAddress((void**)&VT,  g_VT);
    cudaGetSymbolAddress((void**)&P,   g_P);
    cudaGetSymbolAddress((void**)&lp,  g_lp);
    cudaGetSymbolAddress((void**)&lv,  g_l);

    prologue_kernel<<<PRO_BLOCKS, 256>>>(feat1, feat2, Wq, Wk, Wv, Wfc, bv, bfc,
                                         f1, f2, wq, wk, w2, c2);

    cudaFuncSetAttribute(gemm_qkv, cudaFuncAttributeMaxDynamicSharedMemorySize, GEMM_SMEM);
    cudaFuncSetAttribute(gemm_S,   cudaFuncAttributeMaxDynamicSharedMemorySize, GEMM_SMEM);
    cudaFuncSetAttribute(gemm_pv,  cudaFuncAttributeMaxDynamicSharedMemorySize, GEMM_SMEM);

    dim3 gq(2, B_ * S1_ / 128, 3);
    gemm_qkv<<<gq, 256, GEMM_SMEM>>>(f1, f2, wq, wk, w2, bq, bk, zv, Q, K, VT);

    dim3 gs(S2_ / 128, S1_ / 128, B_);
    gemm_S<<<gs, 256, GEMM_SMEM>>>(Q, K, P, lp);

    lreduce_kernel<<<(B_ * S1_ + 255) / 256, 256>>>(lp, lv);

    dim3 gp(F_ / 128, S1_ / 128, B_);
    gemm_pv<<<gp, 256, GEMM_SMEM>>>(P, VT, lv, c2, out);
}